// round 4
// baseline (speedup 1.0000x reference)
#include <cuda_runtime.h>
#include <math.h>

#define HEADS 4
#define RES 28
#define PSZ 14
#define PP 196
#define NB 32
#define NT 784
#define NC 768
#define CH 192
#define NCT 24            // 32-ch tiles for mix
#define EPSF 1e-5f

// ---- persistent device scratch (no allocations allowed) ----
__device__ float g_xp[(size_t)NB * NCT * PP * 32];  // pooled xn, [b][ctile][patch][32]
__device__ float g_inv[NB * HEADS * NT];            // [b][h][t]
__device__ float g_mln[NB * NT];
__device__ float g_vln[NB * NT];
__device__ float g_mr[(size_t)NB * PP * NC];        // scaled pooled mean_r  [b][patch][c]
__device__ float g_vr[(size_t)NB * PP * NC];        // scaled pooled var_r   [b][patch][c]

// ============================================================
// K1: per-token group stats + pooled xp.  block = (b, patch j)
// 192 threads; thread owns 4 consecutive channels (float4).
// ============================================================
__global__ void __launch_bounds__(192) k1_stats(const float* __restrict__ x) {
    int blk = blockIdx.x;
    int b = blk / PP, j = blk % PP;
    int py = j / 14, px = j % 14;
    int tid = threadIdx.x;
    int head = tid / 48;
    int c0 = head * CH + (tid % 48) * 4;
    int baseT = (2 * py) * 28 + 2 * px;

    float4 xv[4];
    float s1[4], s2[4];
    #pragma unroll
    for (int tok = 0; tok < 4; tok++) {
        int t = baseT + (tok >> 1) * 28 + (tok & 1);
        float4 v = __ldg((const float4*)(x + ((size_t)(b * NT + t)) * NC + c0));
        xv[tok] = v;
        s1[tok] = v.x + v.y + v.z + v.w;
        s2[tok] = v.x * v.x + v.y * v.y + v.z * v.z + v.w * v.w;
    }
    #pragma unroll
    for (int off = 8; off > 0; off >>= 1) {
        #pragma unroll
        for (int tok = 0; tok < 4; tok++) {
            s1[tok] += __shfl_down_sync(0xffffffffu, s1[tok], off, 16);
            s2[tok] += __shfl_down_sync(0xffffffffu, s2[tok], off, 16);
        }
    }
    __shared__ float rs1[12][4], rs2[12][4];            // [segment][tok]
    __shared__ float sS1[4][4], sS2[4][4], sInv[4][4];  // [tok][head]
    int seg = tid >> 4;
    if ((tid & 15) == 0) {
        #pragma unroll
        for (int tok = 0; tok < 4; tok++) { rs1[seg][tok] = s1[tok]; rs2[seg][tok] = s2[tok]; }
    }
    __syncthreads();
    if (tid < 16) {
        int tok = tid & 3, h = tid >> 2;
        float S1 = rs1[3 * h][tok] + rs1[3 * h + 1][tok] + rs1[3 * h + 2][tok];
        float S2 = rs2[3 * h][tok] + rs2[3 * h + 1][tok] + rs2[3 * h + 2][tok];
        float inv = rsqrtf(S2 * (1.0f / CH) + EPSF);
        sS1[tok][h] = S1; sS2[tok][h] = S2; sInv[tok][h] = inv;
        int t = baseT + (tok >> 1) * 28 + (tok & 1);
        g_inv[(b * HEADS + h) * NT + t] = inv;
    }
    __syncthreads();
    if (tid < 4) {
        int tok = tid;
        float sx = 0.f, sx2 = 0.f;
        #pragma unroll
        for (int h = 0; h < 4; h++) {
            float inv = sInv[tok][h];
            sx  += sS1[tok][h] * inv;
            sx2 += sS2[tok][h] * inv * inv;
        }
        float mean = sx * (1.0f / NC);
        float var = (sx2 - sx * mean) * (1.0f / (NC - 1));
        int t = baseT + (tok >> 1) * 28 + (tok & 1);
        g_mln[b * NT + t] = mean;
        g_vln[b * NT + t] = var;
    }
    float i0 = sInv[0][head], i1 = sInv[1][head], i2 = sInv[2][head], i3 = sInv[3][head];
    float4 o;
    o.x = 0.25f * (xv[0].x * i0 + xv[1].x * i1 + xv[2].x * i2 + xv[3].x * i3);
    o.y = 0.25f * (xv[0].y * i0 + xv[1].y * i1 + xv[2].y * i2 + xv[3].y * i3);
    o.z = 0.25f * (xv[0].z * i0 + xv[1].z * i1 + xv[2].z * i2 + xv[3].z * i3);
    o.w = 0.25f * (xv[0].w * i0 + xv[1].w * i1 + xv[2].w * i2 + xv[3].w * i3);
    int ct = c0 >> 5, ln = c0 & 31;
    *(float4*)&g_xp[(((size_t)(b * NCT + ct)) * PP + j) * 32 + ln] = o;
}

// ============================================================
// K2mix: separable pos-mix only. block = (b, 32-ch tile), 224 thr.
// Stage-2 writes scaled mean_r/var_r straight to global [b][patch][c].
// ============================================================
#define K2T 224

__global__ void __launch_bounds__(K2T, 3) k2_mix(
        const float* __restrict__ mnw, const float* __restrict__ vnw,
        const float* __restrict__ pw) {
    __shared__ float sT1[6272];   // 196x32 stage-1 mean
    __shared__ float sT2[6272];   // 196x32 stage-1 sq-mean
    __shared__ float sA[196];     // y-factor [iy*14+jy]
    __shared__ float sB[196];     // x-factor [ix*14+jx]

    int b = blockIdx.x;
    int ctile = blockIdx.y;
    int c0 = ctile * 32;
    int h = ctile / 6;
    int tid = threadIdx.x;

    float mwh = 1.0f / (1.0f + expf(-mnw[h]));
    float vwh = 1.0f / (1.0f + expf(-vnw[h]));
    float omm = 1.0f - mwh, omv = 1.0f - vwh;

    if (tid < 14) {                       // Bn: x-axis factor
        int jx = tid;
        float w0 = pw[h * 3 + 0], w2 = pw[h * 3 + 2];
        float s[14]; float mx = -1e30f;
        #pragma unroll
        for (int ix = 0; ix < 14; ix++) {
            float dx = (float)(jx - ix);
            float v = w0 * dx + w2 * dx * dx;
            s[ix] = v; mx = fmaxf(mx, v);
        }
        float sum = 0.f;
        #pragma unroll
        for (int ix = 0; ix < 14; ix++) { s[ix] = expf(s[ix] - mx); sum += s[ix]; }
        float r = 1.0f / sum;
        #pragma unroll
        for (int ix = 0; ix < 14; ix++) sB[ix * 14 + jx] = s[ix] * r;
    } else if (tid >= 32 && tid < 46) {   // An: y-axis factor
        int jy = tid - 32;
        float w1 = pw[h * 3 + 1], w2 = pw[h * 3 + 2];
        float s[14]; float mx = -1e30f;
        #pragma unroll
        for (int iy = 0; iy < 14; iy++) {
            float dy = (float)(jy - iy);
            float v = w1 * dy + w2 * dy * dy;
            s[iy] = v; mx = fmaxf(mx, v);
        }
        float sum = 0.f;
        #pragma unroll
        for (int iy = 0; iy < 14; iy++) { s[iy] = expf(s[iy] - mx); sum += s[iy]; }
        float r = 1.0f / sum;
        #pragma unroll
        for (int iy = 0; iy < 14; iy++) sA[iy * 14 + jy] = s[iy] * r;
    }
    __syncthreads();

    int g = tid >> 5, cl = tid & 31;
    const float* xpg = &g_xp[(((size_t)(b * NCT + ctile)) * PP) * 32];

    // stage 1: contract over ix (global reads, coalesced 128B rows)
    {
        float a1[2][14], a2[2][14];
        #pragma unroll
        for (int jx = 0; jx < 14; jx++) { a1[0][jx] = a1[1][jx] = a2[0][jx] = a2[1][jx] = 0.f; }
        #pragma unroll
        for (int ix = 0; ix < 14; ix++) {
            float v0 = __ldg(xpg + (((g    ) * 14 + ix) << 5) + cl);
            float v1 = __ldg(xpg + (((g + 7) * 14 + ix) << 5) + cl);
            float q0 = v0 * v0, q1 = v1 * v1;
            #pragma unroll
            for (int jx = 0; jx < 14; jx++) {
                float p = sB[ix * 14 + jx];
                a1[0][jx] = fmaf(v0, p, a1[0][jx]);
                a2[0][jx] = fmaf(q0, p, a2[0][jx]);
                a1[1][jx] = fmaf(v1, p, a1[1][jx]);
                a2[1][jx] = fmaf(q1, p, a2[1][jx]);
            }
        }
        #pragma unroll
        for (int jx = 0; jx < 14; jx++) {
            sT1[(((g    ) * 14 + jx) << 5) + cl] = a1[0][jx];
            sT2[(((g    ) * 14 + jx) << 5) + cl] = a2[0][jx];
            sT1[(((g + 7) * 14 + jx) << 5) + cl] = a1[1][jx];
            sT2[(((g + 7) * 14 + jx) << 5) + cl] = a2[1][jx];
        }
    }
    __syncthreads();

    // stage 2: contract over iy; registers -> global (scaled)
    {
        float m[2][14], m2[2][14];
        #pragma unroll
        for (int jx = 0; jx < 14; jx++) { m[0][jx] = m[1][jx] = m2[0][jx] = m2[1][jx] = 0.f; }
        #pragma unroll
        for (int iy = 0; iy < 14; iy++) {
            float p0 = sA[iy * 14 + g];
            float p1 = sA[iy * 14 + g + 7];
            #pragma unroll
            for (int jx = 0; jx < 14; jx++) {
                float t1v = sT1[((iy * 14 + jx) << 5) + cl];
                float t2v = sT2[((iy * 14 + jx) << 5) + cl];
                m [0][jx] = fmaf(p0, t1v, m [0][jx]);
                m2[0][jx] = fmaf(p0, t2v, m2[0][jx]);
                m [1][jx] = fmaf(p1, t1v, m [1][jx]);
                m2[1][jx] = fmaf(p1, t2v, m2[1][jx]);
            }
        }
        size_t base0 = ((size_t)b * PP + (size_t)(g    ) * 14) * NC + c0 + cl;
        size_t base1 = ((size_t)b * PP + (size_t)(g + 7) * 14) * NC + c0 + cl;
        #pragma unroll
        for (int jx = 0; jx < 14; jx++) {
            float mm = m[0][jx];
            g_mr[base0 + (size_t)jx * NC] = omm * mm;
            g_vr[base0 + (size_t)jx * NC] = omv * (m2[0][jx] - mm * mm);
            mm = m[1][jx];
            g_mr[base1 + (size_t)jx * NC] = omm * mm;
            g_vr[base1 + (size_t)jx * NC] = omv * (m2[1][jx] - mm * mm);
        }
    }
}

// ============================================================
// K3epi: pure streaming epilogue.
// block = (patch-row py, 64-ch tile, b); 224 threads, ~15KB smem.
// Covers 56 tokens (2 image rows) x 64 channels.
// ============================================================
#define K3T 224

__global__ void __launch_bounds__(K3T) k3_epi(
        const float* __restrict__ x, const float* __restrict__ weight,
        const float* __restrict__ bias, const float* __restrict__ mnw,
        const float* __restrict__ vnw, float* __restrict__ out) {
    __shared__ float sMR[14 * 64];   // [jx][c]
    __shared__ float sVR[14 * 64];
    __shared__ float sINV[56], sMLN[56], sVLN[56];

    int py = blockIdx.x;
    int ct = blockIdx.y;             // 64-ch tile, 12 total; within one head (192/64=3)
    int b  = blockIdx.z;
    int c0 = ct * 64;
    int h  = ct / 3;
    int tid = threadIdx.x;
    int gt0 = py * 56;               // first global token of the 2-row band

    float mwh = 1.0f / (1.0f + expf(-mnw[h]));
    float vwh = 1.0f / (1.0f + expf(-vnw[h]));

    // stage mr/vr for 14 patches x 64 channels (224 float4 each -> 1 per thread)
    {
        int p = tid >> 4, qq = tid & 15;   // patch 0..13, float4 slot 0..15
        size_t off = ((size_t)b * PP + (size_t)(py * 14 + p)) * NC + c0 + qq * 4;
        ((float4*)sMR)[tid] = *(const float4*)(g_mr + off);
        ((float4*)sVR)[tid] = *(const float4*)(g_vr + off);
    }
    for (int i = tid; i < 56; i += K3T) {
        sINV[i] = g_inv[(b * HEADS + h) * NT + gt0 + i];
        sMLN[i] = mwh * g_mln[b * NT + gt0 + i];
        sVLN[i] = vwh * g_vln[b * NT + gt0 + i];
    }
    __syncthreads();

    int q = tid & 15;                // float4 slot within 64 channels
    int ts = tid >> 4;               // token slot 0..13
    float4 wv = ((const float4*)(weight + c0))[q];
    float4 bv = ((const float4*)(bias   + c0))[q];
    const int rs = NC / 4;
    const float4* xr  = (const float4*)(x   + ((size_t)(b * NT + gt0)) * NC + c0);
    float4*       orr = (float4*)      (out + ((size_t)(b * NT + gt0)) * NC + c0);

    float4 xv[4];
    #pragma unroll
    for (int u = 0; u < 4; u++) {
        int t = ts + u * 14;
        xv[u] = __ldg(&xr[(size_t)t * rs + q]);
    }
    #pragma unroll
    for (int u = 0; u < 4; u++) {
        int t = ts + u * 14;
        int col = (t >= 28) ? (t - 28) : t;
        int jx = col >> 1;
        float inv = sINV[t], ml = sMLN[t], vl = sVLN[t];
        float4 mr = ((const float4*)(sMR + jx * 64))[q];
        float4 vr = ((const float4*)(sVR + jx * 64))[q];
        float4 o;
        o.x = (xv[u].x * inv - (mr.x + ml)) * rsqrtf(vr.x + vl + EPSF) * wv.x + bv.x;
        o.y = (xv[u].y * inv - (mr.y + ml)) * rsqrtf(vr.y + vl + EPSF) * wv.y + bv.y;
        o.z = (xv[u].z * inv - (mr.z + ml)) * rsqrtf(vr.z + vl + EPSF) * wv.z + bv.z;
        o.w = (xv[u].w * inv - (mr.w + ml)) * rsqrtf(vr.w + vl + EPSF) * wv.w + bv.w;
        orr[(size_t)t * rs + q] = o;
    }
}

// ============================================================
extern "C" void kernel_launch(void* const* d_in, const int* in_sizes, int n_in,
                              void* d_out, int out_size) {
    const float* x      = (const float*)d_in[0];
    const float* weight = (const float*)d_in[1];
    const float* bias   = (const float*)d_in[2];
    const float* mnw    = (const float*)d_in[3];
    const float* vnw    = (const float*)d_in[4];
    const float* pw     = (const float*)d_in[5];
    // d_in[6] = pos_b: cancels inside the softmax, unused.
    float* out = (float*)d_out;

    k1_stats<<<NB * PP, 192>>>(x);
    k2_mix<<<dim3(NB, NCT), K2T>>>(mnw, vnw, pw);
    k3_epi<<<dim3(14, 12, NB), K3T>>>(x, weight, bias, mnw, vnw, out);
}

// round 5
// speedup vs baseline: 1.0395x; 1.0395x over previous
#include <cuda_runtime.h>
#include <math.h>

#define HEADS 4
#define RES 28
#define PSZ 14
#define PP 196
#define NB 32
#define NT 784
#define NC 768
#define CH 192
#define NCT 24            // channel tiles of 32
#define EPSF 1e-5f

// ---- persistent device scratch (no allocations allowed) ----
__device__ float g_xp[(size_t)NB * NCT * PP * 32];  // pooled xn, [b][ctile][patch][32]
__device__ float g_inv[NB * HEADS * NT];            // [b][h][t]
__device__ float g_mln[NB * NT];
__device__ float g_vln[NB * NT];

// ============================================================
// K1: per-token group stats + pooled xp.  block = (b, patch j)
// 192 threads; thread owns 4 consecutive channels (float4).
// ============================================================
__global__ void __launch_bounds__(192) k1_stats(const float* __restrict__ x) {
    int blk = blockIdx.x;
    int b = blk / PP, j = blk % PP;
    int py = j / 14, px = j % 14;
    int tid = threadIdx.x;
    int head = tid / 48;
    int c0 = head * CH + (tid % 48) * 4;
    int baseT = (2 * py) * 28 + 2 * px;

    float4 xv[4];
    float s1[4], s2[4];
    #pragma unroll
    for (int tok = 0; tok < 4; tok++) {
        int t = baseT + (tok >> 1) * 28 + (tok & 1);
        float4 v = __ldg((const float4*)(x + ((size_t)(b * NT + t)) * NC + c0));
        xv[tok] = v;
        s1[tok] = v.x + v.y + v.z + v.w;
        s2[tok] = v.x * v.x + v.y * v.y + v.z * v.z + v.w * v.w;
    }
    #pragma unroll
    for (int off = 8; off > 0; off >>= 1) {
        #pragma unroll
        for (int tok = 0; tok < 4; tok++) {
            s1[tok] += __shfl_down_sync(0xffffffffu, s1[tok], off, 16);
            s2[tok] += __shfl_down_sync(0xffffffffu, s2[tok], off, 16);
        }
    }
    __shared__ float rs1[12][4], rs2[12][4];            // [segment][tok]
    __shared__ float sS1[4][4], sS2[4][4], sInv[4][4];  // [tok][head]
    int seg = tid >> 4;
    if ((tid & 15) == 0) {
        #pragma unroll
        for (int tok = 0; tok < 4; tok++) { rs1[seg][tok] = s1[tok]; rs2[seg][tok] = s2[tok]; }
    }
    __syncthreads();
    if (tid < 16) {
        int tok = tid & 3, h = tid >> 2;
        float S1 = rs1[3 * h][tok] + rs1[3 * h + 1][tok] + rs1[3 * h + 2][tok];
        float S2 = rs2[3 * h][tok] + rs2[3 * h + 1][tok] + rs2[3 * h + 2][tok];
        float inv = rsqrtf(S2 * (1.0f / CH) + EPSF);
        sS1[tok][h] = S1; sS2[tok][h] = S2; sInv[tok][h] = inv;
        int t = baseT + (tok >> 1) * 28 + (tok & 1);
        g_inv[(b * HEADS + h) * NT + t] = inv;
    }
    __syncthreads();
    if (tid < 4) {
        int tok = tid;
        float sx = 0.f, sx2 = 0.f;
        #pragma unroll
        for (int h = 0; h < 4; h++) {
            float inv = sInv[tok][h];
            sx  += sS1[tok][h] * inv;
            sx2 += sS2[tok][h] * inv * inv;
        }
        float mean = sx * (1.0f / NC);
        float var = (sx2 - sx * mean) * (1.0f / (NC - 1));
        int t = baseT + (tok >> 1) * 28 + (tok & 1);
        g_mln[b * NT + t] = mean;
        g_vln[b * NT + t] = var;
    }
    float i0 = sInv[0][head], i1 = sInv[1][head], i2 = sInv[2][head], i3 = sInv[3][head];
    float4 o;
    o.x = 0.25f * (xv[0].x * i0 + xv[1].x * i1 + xv[2].x * i2 + xv[3].x * i3);
    o.y = 0.25f * (xv[0].y * i0 + xv[1].y * i1 + xv[2].y * i2 + xv[3].y * i3);
    o.z = 0.25f * (xv[0].z * i0 + xv[1].z * i1 + xv[2].z * i2 + xv[3].z * i3);
    o.w = 0.25f * (xv[0].w * i0 + xv[1].w * i1 + xv[2].w * i2 + xv[3].w * i3);
    int ct = c0 >> 5, ln = c0 & 31;
    *(float4*)&g_xp[(((size_t)(b * NCT + ct)) * PP + j) * 32 + ln] = o;
}

// ============================================================
// K2: separable pos-mix + fused output epilogue.
// block = (b, 32-channel tile). 448 threads = 14 warps; warp g owns ONE row g.
// smem ~61KB dynamic; launch_bounds(448,3) -> 42 warps/SM.
// ============================================================
#define K2T 448
#define SM_FLOATS (12544 + 784 * 3 + 392)

__global__ void __launch_bounds__(K2T, 3) k2_main(
        const float* __restrict__ x, const float* __restrict__ weight,
        const float* __restrict__ bias, const float* __restrict__ mnw,
        const float* __restrict__ vnw, const float* __restrict__ pw,
        float* __restrict__ out) {
    extern __shared__ float sm[];
    float* sT1  = sm;              // 196x32 stage-1 mean     (later: scaled mean_r)
    float* sT2  = sm + 6272;       // 196x32 stage-1 sq-mean  (later: scaled var_r)
    float* sMLN = sm + 12544;      // 784  mw*mean_ln
    float* sVLN = sm + 13328;      // 784  vw*var_ln
    float* sINV = sm + 14112;      // 784  inv for this head
    float* sA   = sm + 14896;      // 196  y-factor [iy*14+jy]
    float* sB   = sm + 15092;      // 196  x-factor [ix*14+jx]

    int b = blockIdx.x;
    int ctile = blockIdx.y;
    int c0 = ctile * 32;
    int h = ctile / 6;             // 6 tiles per head
    int tid = threadIdx.x;

    float mwh = 1.0f / (1.0f + expf(-mnw[h]));
    float vwh = 1.0f / (1.0f + expf(-vnw[h]));
    float omm = 1.0f - mwh, omv = 1.0f - vwh;

    // in-block separable softmax factors (pos_b cancels in softmax)
    if (tid < 14) {                       // Bn: x-axis factor, column jx
        int jx = tid;
        float w0 = pw[h * 3 + 0], w2 = pw[h * 3 + 2];
        float s[14]; float mx = -1e30f;
        #pragma unroll
        for (int ix = 0; ix < 14; ix++) {
            float dx = (float)(jx - ix);
            float v = w0 * dx + w2 * dx * dx;
            s[ix] = v; mx = fmaxf(mx, v);
        }
        float sum = 0.f;
        #pragma unroll
        for (int ix = 0; ix < 14; ix++) { s[ix] = expf(s[ix] - mx); sum += s[ix]; }
        float r = 1.0f / sum;
        #pragma unroll
        for (int ix = 0; ix < 14; ix++) sB[ix * 14 + jx] = s[ix] * r;
    } else if (tid >= 32 && tid < 46) {   // An: y-axis factor, column jy
        int jy = tid - 32;
        float w1 = pw[h * 3 + 1], w2 = pw[h * 3 + 2];
        float s[14]; float mx = -1e30f;
        #pragma unroll
        for (int iy = 0; iy < 14; iy++) {
            float dy = (float)(jy - iy);
            float v = w1 * dy + w2 * dy * dy;
            s[iy] = v; mx = fmaxf(mx, v);
        }
        float sum = 0.f;
        #pragma unroll
        for (int iy = 0; iy < 14; iy++) { s[iy] = expf(s[iy] - mx); sum += s[iy]; }
        float r = 1.0f / sum;
        #pragma unroll
        for (int iy = 0; iy < 14; iy++) sA[iy * 14 + jy] = s[iy] * r;
    }

    // token-stat prologue (vectorized)
    {
        const float4* mg = (const float4*)(g_mln + b * NT);
        const float4* vg = (const float4*)(g_vln + b * NT);
        const float4* ig = (const float4*)(g_inv + (b * HEADS + h) * NT);
        float4* dM = (float4*)sMLN; float4* dV = (float4*)sVLN; float4* dI = (float4*)sINV;
        for (int i = tid; i < NT / 4; i += K2T) {
            float4 m = mg[i], v = vg[i];
            m.x *= mwh; m.y *= mwh; m.z *= mwh; m.w *= mwh;
            v.x *= vwh; v.y *= vwh; v.z *= vwh; v.w *= vwh;
            dM[i] = m; dV[i] = v; dI[i] = ig[i];
        }
    }
    __syncthreads();

    int g = tid >> 5, cl = tid & 31;     // warp g in [0,14), lane cl = channel
    const float* xpg = &g_xp[(((size_t)(b * NCT + ctile)) * PP) * 32];

    // ---- stage 1: warp g owns pooled row iy=g; contract over ix
    {
        float a1[14], a2[14];
        #pragma unroll
        for (int jx = 0; jx < 14; jx++) { a1[jx] = 0.f; a2[jx] = 0.f; }
        #pragma unroll
        for (int ix = 0; ix < 14; ix++) {
            float v0 = __ldg(xpg + ((g * 14 + ix) << 5) + cl);
            float q0 = v0 * v0;
            #pragma unroll
            for (int jx = 0; jx < 14; jx++) {
                float p = sB[ix * 14 + jx];
                a1[jx] = fmaf(v0, p, a1[jx]);
                a2[jx] = fmaf(q0, p, a2[jx]);
            }
        }
        #pragma unroll
        for (int jx = 0; jx < 14; jx++) {
            sT1[((g * 14 + jx) << 5) + cl] = a1[jx];
            sT2[((g * 14 + jx) << 5) + cl] = a2[jx];
        }
    }
    __syncthreads();

    // ---- stage 2: warp g owns output row jy=g; contract over iy, write back in place
    {
        float m[14], m2[14];
        #pragma unroll
        for (int jx = 0; jx < 14; jx++) { m[jx] = 0.f; m2[jx] = 0.f; }
        #pragma unroll
        for (int iy = 0; iy < 14; iy++) {
            float p0 = sA[iy * 14 + g];
            #pragma unroll
            for (int jx = 0; jx < 14; jx++) {
                float t1v = sT1[((iy * 14 + jx) << 5) + cl];
                float t2v = sT2[((iy * 14 + jx) << 5) + cl];
                m [jx] = fmaf(p0, t1v, m [jx]);
                m2[jx] = fmaf(p0, t2v, m2[jx]);
            }
        }
        __syncthreads();   // all reads done before overwrite
        #pragma unroll
        for (int jx = 0; jx < 14; jx++) {
            float mm = m[jx];
            sT1[((g * 14 + jx) << 5) + cl] = omm * mm;
            sT2[((g * 14 + jx) << 5) + cl] = omv * (m2[jx] - mm * mm);
        }
    }
    __syncthreads();

    // ---- fused epilogue: stream x -> out (float4, 7-deep batched loads)
    int q = tid & 7;                     // float4 slot within 32-ch tile
    int ts = tid >> 3;                   // token slot 0..55
    float4 wv = ((const float4*)(weight + c0))[q];
    float4 bv = ((const float4*)(bias   + c0))[q];
    const float4* xr  = (const float4*)(x   + (size_t)b * NT * NC + c0);
    float4*       orr = (float4*)      (out + (size_t)b * NT * NC + c0);
    const int rs = NC / 4;               // row stride in float4

    #pragma unroll 1
    for (int it = 0; it < 2; ++it) {
        float4 xv[7];
        #pragma unroll
        for (int u = 0; u < 7; u++) {
            int t = ts + (it * 7 + u) * 56;
            xv[u] = __ldg(&xr[(size_t)t * rs + q]);
        }
        #pragma unroll
        for (int u = 0; u < 7; u++) {
            int t = ts + (it * 7 + u) * 56;
            unsigned row = (unsigned)t / 28u;
            unsigned col = (unsigned)t - row * 28u;
            int j = (int)((row >> 1) * 14 + (col >> 1));
            float inv = sINV[t], ml = sMLN[t], vl = sVLN[t];
            float4 mr = ((const float4*)(sT1 + (j << 5)))[q];
            float4 vr = ((const float4*)(sT2 + (j << 5)))[q];
            float4 o;
            o.x = (xv[u].x * inv - (mr.x + ml)) * rsqrtf(vr.x + vl + EPSF) * wv.x + bv.x;
            o.y = (xv[u].y * inv - (mr.y + ml)) * rsqrtf(vr.y + vl + EPSF) * wv.y + bv.y;
            o.z = (xv[u].z * inv - (mr.z + ml)) * rsqrtf(vr.z + vl + EPSF) * wv.z + bv.z;
            o.w = (xv[u].w * inv - (mr.w + ml)) * rsqrtf(vr.w + vl + EPSF) * wv.w + bv.w;
            orr[(size_t)t * rs + q] = o;
        }
    }
}

// ============================================================
extern "C" void kernel_launch(void* const* d_in, const int* in_sizes, int n_in,
                              void* d_out, int out_size) {
    const float* x      = (const float*)d_in[0];
    const float* weight = (const float*)d_in[1];
    const float* bias   = (const float*)d_in[2];
    const float* mnw    = (const float*)d_in[3];
    const float* vnw    = (const float*)d_in[4];
    const float* pw     = (const float*)d_in[5];
    // d_in[6] = pos_b: cancels inside the softmax, unused.
    float* out = (float*)d_out;

    cudaFuncSetAttribute(k2_main, cudaFuncAttributeMaxDynamicSharedMemorySize,
                         SM_FLOATS * (int)sizeof(float));

    k1_stats<<<NB * PP, 192>>>(x);
    k2_main<<<dim3(NB, NCT), K2T, SM_FLOATS * sizeof(float)>>>(
        x, weight, bias, mnw, vnw, pw, out);
}

// round 6
// speedup vs baseline: 1.2229x; 1.1764x over previous
#include <cuda_runtime.h>
#include <math.h>

#define HEADS 4
#define RES 28
#define PSZ 14
#define PP 196
#define NB 32
#define NT 784
#define NC 768
#define CH 192
#define NCT 24            // channel tiles of 32
#define EPSF 1e-5f

// ---- persistent device scratch (no allocations allowed) ----
__device__ float g_xp[(size_t)NB * NCT * PP * 32];  // pooled xn, [b][ctile][patch][32]
__device__ float g_inv[NB * HEADS * NT];            // [b][h][t]
__device__ float g_mln[NB * NT];
__device__ float g_vln[NB * NT];

// ============================================================
// K1: per-token group stats + pooled xp.  block = (b, patch j)
// 192 threads; thread owns 4 consecutive channels (float4).
// ============================================================
__global__ void __launch_bounds__(192) k1_stats(const float* __restrict__ x) {
    int blk = blockIdx.x;
    int b = blk / PP, j = blk % PP;
    int py = j / 14, px = j % 14;
    int tid = threadIdx.x;
    int head = tid / 48;
    int c0 = head * CH + (tid % 48) * 4;
    int baseT = (2 * py) * 28 + 2 * px;

    float4 xv[4];
    float s1[4], s2[4];
    #pragma unroll
    for (int tok = 0; tok < 4; tok++) {
        int t = baseT + (tok >> 1) * 28 + (tok & 1);
        float4 v = __ldg((const float4*)(x + ((size_t)(b * NT + t)) * NC + c0));
        xv[tok] = v;
        s1[tok] = v.x + v.y + v.z + v.w;
        s2[tok] = v.x * v.x + v.y * v.y + v.z * v.z + v.w * v.w;
    }
    #pragma unroll
    for (int off = 8; off > 0; off >>= 1) {
        #pragma unroll
        for (int tok = 0; tok < 4; tok++) {
            s1[tok] += __shfl_down_sync(0xffffffffu, s1[tok], off, 16);
            s2[tok] += __shfl_down_sync(0xffffffffu, s2[tok], off, 16);
        }
    }
    __shared__ float rs1[12][4], rs2[12][4];            // [segment][tok]
    __shared__ float sS1[4][4], sS2[4][4], sInv[4][4];  // [tok][head]
    int seg = tid >> 4;
    if ((tid & 15) == 0) {
        #pragma unroll
        for (int tok = 0; tok < 4; tok++) { rs1[seg][tok] = s1[tok]; rs2[seg][tok] = s2[tok]; }
    }
    __syncthreads();
    if (tid < 16) {
        int tok = tid & 3, h = tid >> 2;
        float S1 = rs1[3 * h][tok] + rs1[3 * h + 1][tok] + rs1[3 * h + 2][tok];
        float S2 = rs2[3 * h][tok] + rs2[3 * h + 1][tok] + rs2[3 * h + 2][tok];
        float inv = rsqrtf(S2 * (1.0f / CH) + EPSF);
        sS1[tok][h] = S1; sS2[tok][h] = S2; sInv[tok][h] = inv;
        int t = baseT + (tok >> 1) * 28 + (tok & 1);
        g_inv[(b * HEADS + h) * NT + t] = inv;
    }
    __syncthreads();
    if (tid < 4) {
        int tok = tid;
        float sx = 0.f, sx2 = 0.f;
        #pragma unroll
        for (int h = 0; h < 4; h++) {
            float inv = sInv[tok][h];
            sx  += sS1[tok][h] * inv;
            sx2 += sS2[tok][h] * inv * inv;
        }
        float mean = sx * (1.0f / NC);
        float var = (sx2 - sx * mean) * (1.0f / (NC - 1));
        int t = baseT + (tok >> 1) * 28 + (tok & 1);
        g_mln[b * NT + t] = mean;
        g_vln[b * NT + t] = var;
    }
    float i0 = sInv[0][head], i1 = sInv[1][head], i2 = sInv[2][head], i3 = sInv[3][head];
    float4 o;
    o.x = 0.25f * (xv[0].x * i0 + xv[1].x * i1 + xv[2].x * i2 + xv[3].x * i3);
    o.y = 0.25f * (xv[0].y * i0 + xv[1].y * i1 + xv[2].y * i2 + xv[3].y * i3);
    o.z = 0.25f * (xv[0].z * i0 + xv[1].z * i1 + xv[2].z * i2 + xv[3].z * i3);
    o.w = 0.25f * (xv[0].w * i0 + xv[1].w * i1 + xv[2].w * i2 + xv[3].w * i3);
    int ct = c0 >> 5, ln = c0 & 31;
    *(float4*)&g_xp[(((size_t)(b * NCT + ct)) * PP + j) * 32 + ln] = o;
}

// ============================================================
// K2: separable pos-mix + fused output epilogue.
// block = (b, 32-channel tile). 224 threads = 7 warps; warp g owns rows g, g+7.
// smem ~55KB; launch_bounds(224,4) -> 28 warps/SM, no spill (split stages).
// ============================================================
#define K2T 224
#define SM_FLOATS (12544 + 784 + 392)   // sT1,sT2 + sINV + sA,sB

__global__ void __launch_bounds__(K2T, 4) k2_main(
        const float* __restrict__ x, const float* __restrict__ weight,
        const float* __restrict__ bias, const float* __restrict__ mnw,
        const float* __restrict__ vnw, const float* __restrict__ pw,
        float* __restrict__ out) {
    extern __shared__ float sm[];
    float* sT1  = sm;              // 196x32 stage-1 mean     (later: scaled mean_r)
    float* sT2  = sm + 6272;       // 196x32 stage-1 sq-mean  (later: scaled var_r)
    float* sINV = sm + 12544;      // 784  inv for this head
    float* sA   = sm + 13328;      // 196  y-factor [iy*14+jy]
    float* sB   = sm + 13524;      // 196  x-factor [ix*14+jx]

    int b = blockIdx.x;
    int ctile = blockIdx.y;
    int c0 = ctile * 32;
    int h = ctile / 6;             // 6 tiles per head
    int tid = threadIdx.x;

    float mwh = 1.0f / (1.0f + expf(-mnw[h]));
    float vwh = 1.0f / (1.0f + expf(-vnw[h]));
    float omm = 1.0f - mwh, omv = 1.0f - vwh;

    // in-block separable softmax factors (pos_b cancels in softmax)
    if (tid < 14) {                       // Bn: x-axis factor, column jx
        int jx = tid;
        float w0 = pw[h * 3 + 0], w2 = pw[h * 3 + 2];
        float s[14]; float mx = -1e30f;
        #pragma unroll
        for (int ix = 0; ix < 14; ix++) {
            float dx = (float)(jx - ix);
            float v = w0 * dx + w2 * dx * dx;
            s[ix] = v; mx = fmaxf(mx, v);
        }
        float sum = 0.f;
        #pragma unroll
        for (int ix = 0; ix < 14; ix++) { s[ix] = expf(s[ix] - mx); sum += s[ix]; }
        float r = 1.0f / sum;
        #pragma unroll
        for (int ix = 0; ix < 14; ix++) sB[ix * 14 + jx] = s[ix] * r;
    } else if (tid >= 32 && tid < 46) {   // An: y-axis factor, column jy
        int jy = tid - 32;
        float w1 = pw[h * 3 + 1], w2 = pw[h * 3 + 2];
        float s[14]; float mx = -1e30f;
        #pragma unroll
        for (int iy = 0; iy < 14; iy++) {
            float dy = (float)(jy - iy);
            float v = w1 * dy + w2 * dy * dy;
            s[iy] = v; mx = fmaxf(mx, v);
        }
        float sum = 0.f;
        #pragma unroll
        for (int iy = 0; iy < 14; iy++) { s[iy] = expf(s[iy] - mx); sum += s[iy]; }
        float r = 1.0f / sum;
        #pragma unroll
        for (int iy = 0; iy < 14; iy++) sA[iy * 14 + jy] = s[iy] * r;
    }

    // token-stat prologue (inv only; mean/var loaded in epilogue from L2)
    {
        const float4* ig = (const float4*)(g_inv + (b * HEADS + h) * NT);
        float4* dI = (float4*)sINV;
        for (int i = tid; i < NT / 4; i += K2T) dI[i] = ig[i];
    }
    __syncthreads();

    int g = tid >> 5, cl = tid & 31;     // warp g in [0,7), rows g and g+7
    const float* xpg = &g_xp[(((size_t)(b * NCT + ctile)) * PP) * 32];

    // ---- stage 1: contract over ix, split jx into halves of 7 (reg diet)
    #pragma unroll 1
    for (int hf = 0; hf < 2; hf++) {
        int j0 = hf * 7;
        float a1[2][7], a2[2][7];
        #pragma unroll
        for (int jx = 0; jx < 7; jx++) { a1[0][jx] = a1[1][jx] = a2[0][jx] = a2[1][jx] = 0.f; }
        #pragma unroll
        for (int ix = 0; ix < 14; ix++) {
            float v0 = __ldg(xpg + (((g    ) * 14 + ix) << 5) + cl);
            float v1 = __ldg(xpg + (((g + 7) * 14 + ix) << 5) + cl);
            float q0 = v0 * v0, q1 = v1 * v1;
            #pragma unroll
            for (int jx = 0; jx < 7; jx++) {
                float p = sB[ix * 14 + j0 + jx];
                a1[0][jx] = fmaf(v0, p, a1[0][jx]);
                a2[0][jx] = fmaf(q0, p, a2[0][jx]);
                a1[1][jx] = fmaf(v1, p, a1[1][jx]);
                a2[1][jx] = fmaf(q1, p, a2[1][jx]);
            }
        }
        #pragma unroll
        for (int jx = 0; jx < 7; jx++) {
            sT1[(((g    ) * 14 + j0 + jx) << 5) + cl] = a1[0][jx];
            sT2[(((g    ) * 14 + j0 + jx) << 5) + cl] = a2[0][jx];
            sT1[(((g + 7) * 14 + j0 + jx) << 5) + cl] = a1[1][jx];
            sT2[(((g + 7) * 14 + j0 + jx) << 5) + cl] = a2[1][jx];
        }
    }
    __syncthreads();

    // ---- stage 2: contract over iy, split jx halves (read/write col-blocks
    // are disjoint per half, so one barrier between compute and write suffices)
    #pragma unroll 1
    for (int hf = 0; hf < 2; hf++) {
        int j0 = hf * 7;
        float m[2][7], m2[2][7];
        #pragma unroll
        for (int jx = 0; jx < 7; jx++) { m[0][jx] = m[1][jx] = m2[0][jx] = m2[1][jx] = 0.f; }
        #pragma unroll
        for (int iy = 0; iy < 14; iy++) {
            float p0 = sA[iy * 14 + g];
            float p1 = sA[iy * 14 + g + 7];
            #pragma unroll
            for (int jx = 0; jx < 7; jx++) {
                float t1v = sT1[((iy * 14 + j0 + jx) << 5) + cl];
                float t2v = sT2[((iy * 14 + j0 + jx) << 5) + cl];
                m [0][jx] = fmaf(p0, t1v, m [0][jx]);
                m2[0][jx] = fmaf(p0, t2v, m2[0][jx]);
                m [1][jx] = fmaf(p1, t1v, m [1][jx]);
                m2[1][jx] = fmaf(p1, t2v, m2[1][jx]);
            }
        }
        __syncthreads();   // all reads of this col-block done before overwrite
        #pragma unroll
        for (int jx = 0; jx < 7; jx++) {
            float mm = m[0][jx];
            sT1[(((g    ) * 14 + j0 + jx) << 5) + cl] = omm * mm;
            sT2[(((g    ) * 14 + j0 + jx) << 5) + cl] = omv * (m2[0][jx] - mm * mm);
            mm = m[1][jx];
            sT1[(((g + 7) * 14 + j0 + jx) << 5) + cl] = omm * mm;
            sT2[(((g + 7) * 14 + j0 + jx) << 5) + cl] = omv * (m2[1][jx] - mm * mm);
        }
    }
    __syncthreads();

    // ---- fused epilogue: stream x -> out (float4, 4-deep batched loads)
    int q = tid & 7;                     // float4 slot within 32-ch tile
    int tb = tid >> 3;                   // token slot 0..27
    float4 wv = ((const float4*)(weight + c0))[q];
    float4 bv = ((const float4*)(bias   + c0))[q];
    const float* mlg = g_mln + b * NT;
    const float* vlg = g_vln + b * NT;
    const float4* xr  = (const float4*)(x   + (size_t)b * NT * NC + c0);
    float4*       orr = (float4*)      (out + (size_t)b * NT * NC + c0);
    const int rs = NC / 4;               // row stride in float4

    #pragma unroll 1
    for (int it = 0; it < 7; ++it) {
        float4 xv[4];
        float ml[4], vl[4];
        #pragma unroll
        for (int u = 0; u < 4; u++) {
            int t = tb + (it * 4 + u) * 28;
            xv[u] = __ldg(&xr[(size_t)t * rs + q]);
            ml[u] = __ldg(mlg + t);
            vl[u] = __ldg(vlg + t);
        }
        #pragma unroll
        for (int u = 0; u < 4; u++) {
            int t = tb + (it * 4 + u) * 28;
            unsigned row = (unsigned)t / 28u;
            unsigned col = (unsigned)t - row * 28u;
            int j = (int)((row >> 1) * 14 + (col >> 1));
            float inv = sINV[t];
            float mlv = mwh * ml[u], vlv = vwh * vl[u];
            float4 mr = ((const float4*)(sT1 + (j << 5)))[q];
            float4 vr = ((const float4*)(sT2 + (j << 5)))[q];
            float4 o;
            o.x = (xv[u].x * inv - (mr.x + mlv)) * rsqrtf(vr.x + vlv + EPSF) * wv.x + bv.x;
            o.y = (xv[u].y * inv - (mr.y + mlv)) * rsqrtf(vr.y + vlv + EPSF) * wv.y + bv.y;
            o.z = (xv[u].z * inv - (mr.z + mlv)) * rsqrtf(vr.z + vlv + EPSF) * wv.z + bv.z;
            o.w = (xv[u].w * inv - (mr.w + mlv)) * rsqrtf(vr.w + vlv + EPSF) * wv.w + bv.w;
            orr[(size_t)t * rs + q] = o;
        }
    }
}

// ============================================================
extern "C" void kernel_launch(void* const* d_in, const int* in_sizes, int n_in,
                              void* d_out, int out_size) {
    const float* x      = (const float*)d_in[0];
    const float* weight = (const float*)d_in[1];
    const float* bias   = (const float*)d_in[2];
    const float* mnw    = (const float*)d_in[3];
    const float* vnw    = (const float*)d_in[4];
    const float* pw     = (const float*)d_in[5];
    // d_in[6] = pos_b: cancels inside the softmax, unused.
    float* out = (float*)d_out;

    cudaFuncSetAttribute(k2_main, cudaFuncAttributeMaxDynamicSharedMemorySize,
                         SM_FLOATS * (int)sizeof(float));

    k1_stats<<<NB * PP, 192>>>(x);
    k2_main<<<dim3(NB, NCT), K2T, SM_FLOATS * sizeof(float)>>>(
        x, weight, bias, mnw, vnw, pw, out);
}